// round 3
// baseline (speedup 1.0000x reference)
#include <cuda_runtime.h>
#include <cuda_bf16.h>
#include <cstdint>

typedef unsigned long long ull;

// packed fp32x2 FMA: d = a*b + d (lanewise on the two fp32 halves)
__device__ __forceinline__ void fma2(ull& d, ull a, ull b) {
    asm("fma.rn.f32x2 %0, %1, %2, %0;" : "+l"(d) : "l"(a), "l"(b));
}

// broadcast a scalar into both fp32 lanes of a 64-bit register
__device__ __forceinline__ ull pack2(float v) {
    ull r;
    asm("mov.b64 %0, {%1, %1};" : "=l"(r) : "f"(v));
    return r;
}

__device__ __forceinline__ void unpack2(ull a, float& lo, float& hi) {
    asm("mov.b64 {%0, %1}, %2;" : "=f"(lo), "=f"(hi) : "l"(a));
}

// Conv2d: x[32,128,56,56] * w[256,128,3,3] + b[256] -> out[32,256,56,56]
// stride 1, pad 1. Block: 64 out-channels x 4 rows x 56 cols for one image.
// Thread: 8 channels x 7 pixels, accumulated as 4 f32x2 pairs x 7.
__global__ void __launch_bounds__(256, 2)
conv2d_kernel(const float* __restrict__ x,
              const float* __restrict__ wgt,
              const float* __restrict__ bias,
              float* __restrict__ out) {
    __shared__ float s_x[8][6][58];    // [c][row (h0-1..h0+4)][col (w=-1..56)+1]
    // [(c*9 + r*3 + s)][local k], padded row (66 floats = 264 B, 8B-aligned)
    // so the transposed STS pattern rotates banks instead of hammering one.
    __shared__ float s_w[72][66];

    const int tid = threadIdx.x;
    const int tz = tid & 7;            // channel group (8 ch each)
    const int tx = (tid >> 3) & 7;     // pixel group (7 px each)
    const int ty = tid >> 6;           // row within tile (0..3)

    const int k0 = blockIdx.x * 64;
    const int h0 = blockIdx.y * 4;
    const int n  = blockIdx.z;

    ull acc[4][7];
    #pragma unroll
    for (int i = 0; i < 4; ++i)
        #pragma unroll
        for (int p = 0; p < 7; ++p) acc[i][p] = 0ull;

    for (int c0 = 0; c0 < 128; c0 += 8) {
        __syncthreads();   // protect smem from previous chunk's readers

        // ---- load input tile [8][6][58] with zero-padded halo ----
        for (int idx = tid; idx < 8 * 6 * 58; idx += 256) {
            int c   = idx / 348;
            int rem = idx - c * 348;
            int rr  = rem / 58;
            int col = rem - rr * 58;
            int h_in = h0 - 1 + rr;
            int w_in = col - 1;
            float v = 0.0f;
            if ((unsigned)h_in < 56u && (unsigned)w_in < 56u)
                v = x[((size_t)(n * 128 + c0 + c) * 56 + h_in) * 56 + w_in];
            s_x[c][rr][col] = v;
        }

        // ---- load weight tile, transposed so local-k is contiguous in smem.
        // Index mapping: crs fast (contiguous 72-float runs in gmem per k),
        // kcl slow -> coalesced 288B bursts instead of stride-4.6KB gathers.
        for (int idx = tid; idx < 8 * 9 * 64; idx += 256) {
            int kcl = idx / 72;
            int crs = idx - kcl * 72;    // c*9 + r*3 + s, contiguous in OIHW
            s_w[crs][kcl] = wgt[(size_t)(k0 + kcl) * 1152 + c0 * 9 + crs];
        }
        __syncthreads();

        // ---- compute ----
        #pragma unroll 2
        for (int c = 0; c < 8; ++c) {
            #pragma unroll
            for (int r = 0; r < 3; ++r) {
                const float* xr = &s_x[c][ty + r][tx * 7];
                ull xp[9];
                #pragma unroll
                for (int j = 0; j < 9; ++j) xp[j] = pack2(xr[j]);

                #pragma unroll
                for (int s = 0; s < 3; ++s) {
                    const ull* wr = (const ull*)&s_w[c * 9 + r * 3 + s][tz * 8];
                    ull w0 = wr[0], w1 = wr[1], w2 = wr[2], w3 = wr[3];
                    #pragma unroll
                    for (int p = 0; p < 7; ++p) {
                        ull xv = xp[s + p];
                        fma2(acc[0][p], w0, xv);
                        fma2(acc[1][p], w1, xv);
                        fma2(acc[2][p], w2, xv);
                        fma2(acc[3][p], w3, xv);
                    }
                }
            }
        }
    }

    // ---- epilogue: bias + store ----
    const int h = h0 + ty;
    const int wbase = tx * 7;
    #pragma unroll
    for (int i2 = 0; i2 < 4; ++i2) {
        const int kc = k0 + tz * 8 + 2 * i2;
        const float b0 = bias[kc];
        const float b1 = bias[kc + 1];
        float* o0 = &out[((size_t)(n * 256 + kc) * 56 + h) * 56 + wbase];
        float* o1 = o0 + 3136;
        #pragma unroll
        for (int p = 0; p < 7; ++p) {
            float lo, hi;
            unpack2(acc[i2][p], lo, hi);
            o0[p] = lo + b0;
            o1[p] = hi + b1;
        }
    }
}

extern "C" void kernel_launch(void* const* d_in, const int* in_sizes, int n_in,
                              void* d_out, int out_size) {
    const float* x    = (const float*)d_in[0];   // [32,128,56,56]
    const float* wgt  = (const float*)d_in[1];   // [256,128,3,3]
    const float* bias = (const float*)d_in[2];   // [256]
    float* out = (float*)d_out;                  // [32,256,56,56]

    dim3 grid(4, 14, 32);   // (k-block, h-block, n)
    dim3 block(256);
    conv2d_kernel<<<grid, block>>>(x, wgt, bias, out);
}

// round 9
// speedup vs baseline: 1.0827x; 1.0827x over previous
#include <cuda_runtime.h>
#include <cuda_bf16.h>
#include <cstdint>

typedef unsigned long long ull;

// packed fp32x2 FMA: d = a*b + d (lanewise on the two fp32 halves)
__device__ __forceinline__ void fma2(ull& d, ull a, ull b) {
    asm("fma.rn.f32x2 %0, %1, %2, %0;" : "+l"(d) : "l"(a), "l"(b));
}

// broadcast a scalar into both fp32 lanes of a 64-bit register
__device__ __forceinline__ ull pack2(float v) {
    ull r;
    asm("mov.b64 %0, {%1, %1};" : "=l"(r) : "f"(v));
    return r;
}

__device__ __forceinline__ void unpack2(ull a, float& lo, float& hi) {
    asm("mov.b64 {%0, %1}, %2;" : "=f"(lo), "=f"(hi) : "l"(a));
}

// Conv2d: x[32,128,56,56] * w[256,128,3,3] + b[256] -> out[32,256,56,56]
// stride 1, pad 1. Block: 64 out-channels x 4 rows x 56 cols for one image.
// Thread: 8 channels x 7 pixels, accumulated as 4 f32x2 pairs x 7.
__global__ void __launch_bounds__(256, 2)
conv2d_kernel(const float* __restrict__ x,
              const float* __restrict__ wgt,
              const float* __restrict__ bias,
              float* __restrict__ out) {
    __shared__ float s_x[8][6][58];    // [c][row (h0-1..h0+4)][col (w=-1..56)+1]
    // Weight tile as channel-PAIRS: s_w2[crs][j*8 + tz] = channels
    // (tz*8 + 2j, tz*8 + 2j + 1). Warp-wide LDS.64 at [crs][j*8+tz] reads 8
    // CONSECUTIVE 8B words (64B, 16 banks) -> conflict-free (was 2-way at
    // tz*32B stride). Row padded to 33 ull to rotate banks across crs.
    __shared__ ull s_w2[72][33];

    const int tid = threadIdx.x;
    const int tz = tid & 7;            // channel group (8 ch each)
    const int tx = (tid >> 3) & 7;     // pixel group (7 px each)
    const int ty = tid >> 6;           // row within tile (0..3)

    const int k0 = blockIdx.x * 64;
    const int h0 = blockIdx.y * 4;
    const int n  = blockIdx.z;

    ull acc[4][7];
    #pragma unroll
    for (int i = 0; i < 4; ++i)
        #pragma unroll
        for (int p = 0; p < 7; ++p) acc[i][p] = 0ull;

    for (int c0 = 0; c0 < 128; c0 += 8) {
        __syncthreads();   // protect smem from previous chunk's readers

        // ---- load input tile [8][6][58] with zero-padded halo ----
        for (int idx = tid; idx < 8 * 6 * 58; idx += 256) {
            int c   = idx / 348;
            int rem = idx - c * 348;
            int rr  = rem / 58;
            int col = rem - rr * 58;
            int h_in = h0 - 1 + rr;
            int w_in = col - 1;
            float v = 0.0f;
            if ((unsigned)h_in < 56u && (unsigned)w_in < 56u)
                v = x[((size_t)(n * 128 + c0 + c) * 56 + h_in) * 56 + w_in];
            s_x[c][rr][col] = v;
        }

        // ---- load weight tile into pair layout.
        // Gmem side stays coalesced: crs fast (contiguous 72-float runs per k).
        // Smem side scatters to [crs][(j*8+tz)*2+half] (float view).
        for (int idx = tid; idx < 8 * 9 * 64; idx += 256) {
            int kcl = idx / 72;          // local out-channel 0..63
            int crs = idx - kcl * 72;    // c*9 + r*3 + s, contiguous in OIHW
            int wtz  = kcl >> 3;         // which tz owns this channel
            int j    = (kcl >> 1) & 3;   // pair index within tz's 8 channels
            int half = kcl & 1;          // lo/hi half of the pair
            float* dstf = (float*)&s_w2[crs][j * 8 + wtz];
            dstf[half] = wgt[(size_t)(k0 + kcl) * 1152 + c0 * 9 + crs];
        }
        __syncthreads();

        // ---- compute ----
        #pragma unroll 2
        for (int c = 0; c < 8; ++c) {
            #pragma unroll
            for (int r = 0; r < 3; ++r) {
                const float* xr = &s_x[c][ty + r][tx * 7];
                ull xp[9];
                #pragma unroll
                for (int j = 0; j < 9; ++j) xp[j] = pack2(xr[j]);

                #pragma unroll
                for (int s = 0; s < 3; ++s) {
                    const ull* wr = &s_w2[c * 9 + r * 3 + s][tz];
                    ull w0 = wr[0], w1 = wr[8], w2 = wr[16], w3 = wr[24];
                    #pragma unroll
                    for (int p = 0; p < 7; ++p) {
                        ull xv = xp[s + p];
                        fma2(acc[0][p], w0, xv);
                        fma2(acc[1][p], w1, xv);
                        fma2(acc[2][p], w2, xv);
                        fma2(acc[3][p], w3, xv);
                    }
                }
            }
        }
    }

    // ---- epilogue: bias + store ----
    const int h = h0 + ty;
    const int wbase = tx * 7;
    #pragma unroll
    for (int i2 = 0; i2 < 4; ++i2) {
        const int kc = k0 + tz * 8 + 2 * i2;
        const float b0 = bias[kc];
        const float b1 = bias[kc + 1];
        float* o0 = &out[((size_t)(n * 256 + kc) * 56 + h) * 56 + wbase];
        float* o1 = o0 + 3136;
        #pragma unroll
        for (int p = 0; p < 7; ++p) {
            float lo, hi;
            unpack2(acc[i2][p], lo, hi);
            o0[p] = lo + b0;
            o1[p] = hi + b1;
        }
    }
}

extern "C" void kernel_launch(void* const* d_in, const int* in_sizes, int n_in,
                              void* d_out, int out_size) {
    const float* x    = (const float*)d_in[0];   // [32,128,56,56]
    const float* wgt  = (const float*)d_in[1];   // [256,128,3,3]
    const float* bias = (const float*)d_in[2];   // [256]
    float* out = (float*)d_out;                  // [32,256,56,56]

    dim3 grid(4, 14, 32);   // (k-block, h-block, n)
    dim3 block(256);
    conv2d_kernel<<<grid, block>>>(x, wgt, bias, out);
}

// round 16
// speedup vs baseline: 2.1410x; 1.9775x over previous
#include <cuda_runtime.h>
#include <cuda_bf16.h>
#include <cstdint>

// Conv2d: x[32,128,56,56] * w[256,128,3,3] + b[256] -> out[32,256,56,56], pad 1.
// Implicit GEMM on HMMA (mma.sync bf16, compute_103-safe; tcgen05 rejected by
// harness toolchain). fp32 emulated via bf16 hi/lo split: D = hh + hl + lh.
// CTA: 128 out-ch x 64 px (8x8 tile). Warp: 32k x 32px. K = 2 cb x 9 rs x 4 c16.
// B tiles are [n][k] row-major == the mma ".col" B^T layout, so B uses
// NON-trans ldmatrix (R15 bug: .trans double-transposed -> rel_err 1.32).

#define SWZ(o) ((o) ^ (((o) >> 3) & 0x70))

// smem layout (bytes); A/B tiles SW128-swizzled, 1024-aligned
#define OFF_STH   128      // staged x hi: [10][10][66] bf16 = 13200 B
#define OFF_STL   13376    // staged x lo
#define OFF_AH    28672    // A hi: [128 k][64 c] bf16 = 16384 B
#define OFF_AL    45056    // A lo
#define OFF_BH    61440    // B hi: [64 px][64 c] bf16 = 8192 B
#define OFF_BL    69632    // B lo
#define SMEM_TOTAL 77824

// weights transposed + bf16-split: [rs][k][c], built once per launch
static __device__ __nv_bfloat16 g_wt_hi[9 * 256 * 128];
static __device__ __nv_bfloat16 g_wt_lo[9 * 256 * 128];

__global__ void prep_w_kernel(const float* __restrict__ wgt) {
    int idx = blockIdx.x * 256 + threadIdx.x;
    if (idx >= 9 * 256 * 128) return;
    int c  = idx & 127;
    int k  = (idx >> 7) & 255;
    int rs = idx >> 15;
    float v = wgt[k * 1152 + c * 9 + rs];
    __nv_bfloat16 hi = __float2bfloat16(v);
    g_wt_hi[idx] = hi;
    g_wt_lo[idx] = __float2bfloat16(v - __bfloat162float(hi));
}

__device__ __forceinline__ void ldsm_x4(uint32_t* r, uint32_t a) {
    asm volatile("ldmatrix.sync.aligned.m8n8.x4.shared.b16 {%0,%1,%2,%3}, [%4];"
                 : "=r"(r[0]), "=r"(r[1]), "=r"(r[2]), "=r"(r[3]) : "r"(a));
}
__device__ __forceinline__ void mma_bf16(float* d, const uint32_t* a, const uint32_t* b) {
    asm volatile("mma.sync.aligned.m16n8k16.row.col.f32.bf16.bf16.f32 "
                 "{%0,%1,%2,%3}, {%4,%5,%6,%7}, {%8,%9}, {%0,%1,%2,%3};"
                 : "+f"(d[0]), "+f"(d[1]), "+f"(d[2]), "+f"(d[3])
                 : "r"(a[0]), "r"(a[1]), "r"(a[2]), "r"(a[3]), "r"(b[0]), "r"(b[1]));
}

__global__ void __launch_bounds__(256, 2)
conv_mma_kernel(const float* __restrict__ x, const float* __restrict__ bias,
                float* __restrict__ out) {
    extern __shared__ char smem[];
    uint32_t sb;
    asm("{ .reg .u64 t; cvta.to.shared.u64 t, %1; cvt.u32.u64 %0, t; }" : "=r"(sb) : "l"(smem));
    const int tid  = threadIdx.x;
    const int wid  = tid >> 5;
    const int lane = tid & 31;
    const int k0   = blockIdx.x * 128;
    const int tile = blockIdx.y;
    const int n    = blockIdx.z;
    const int ph   = (tile / 7) * 8;
    const int pw   = (tile % 7) * 8;

    const int k_w  = (wid >> 1) * 32;   // warp's k quadrant (32 rows)
    const int px_w = (wid & 1) * 32;    // warp's px half (32 cols)

    __nv_bfloat16* stH = (__nv_bfloat16*)(smem + OFF_STH);
    __nv_bfloat16* stL = (__nv_bfloat16*)(smem + OFF_STL);

    float acc[2][4][4];
    #pragma unroll
    for (int mt = 0; mt < 2; ++mt)
        #pragma unroll
        for (int nt = 0; nt < 4; ++nt)
            #pragma unroll
            for (int i = 0; i < 4; ++i) acc[mt][nt][i] = 0.0f;

    for (int cb = 0; cb < 2; ++cb) {
        __syncthreads();   // staged buffer reuse guard

        // ---- stage x chunk [64 c][10 h][10 w] -> staged[hh][ww][c] bf16 hi/lo ----
        for (int e = tid; e < 6400; e += 256) {
            int c  = e / 100;
            int r2 = e - c * 100;
            int hh = r2 / 10;
            int ww = r2 - hh * 10;
            int h = ph + hh - 1, w = pw + ww - 1;
            float v = 0.0f;
            if ((unsigned)h < 56u && (unsigned)w < 56u)
                v = x[((size_t)(n * 128 + cb * 64 + c) * 56 + h) * 56 + w];
            __nv_bfloat16 hi = __float2bfloat16(v);
            int si = (hh * 10 + ww) * 66 + c;
            stH[si] = hi;
            stL[si] = __float2bfloat16(v - __bfloat162float(hi));
        }
        __syncthreads();

        for (int rs = 0; rs < 9; ++rs) {
            const int r = rs / 3, s = rs - r * 3;

            // ---- build B tiles [64 px][64 c] (SW128) from staged ----
            for (int e = tid; e < 2048; e += 256) {
                int px = e >> 5, cp = e & 31;
                int py = px >> 3, pxx = px & 7;
                int si = ((py + r) * 10 + (pxx + s)) * 66 + cp * 2;
                uint32_t vh = *(const uint32_t*)(stH + si);
                uint32_t vl = *(const uint32_t*)(stL + si);
                int bo = px * 128 + cp * 4;
                *(uint32_t*)(smem + OFF_BH + SWZ(bo)) = vh;
                *(uint32_t*)(smem + OFF_BL + SWZ(bo)) = vl;
            }
            // ---- load A tiles [128 k][64 c] (SW128) from pre-transposed weights ----
            for (int q = tid; q < 1024; q += 256) {
                int k = q >> 3, c16 = q & 7;
                size_t go = ((size_t)(rs * 256 + k0 + k)) * 128 + cb * 64 + c16 * 8;
                uint4 vh = *(const uint4*)((const char*)g_wt_hi + go * 2);
                uint4 vl = *(const uint4*)((const char*)g_wt_lo + go * 2);
                int ao = k * 128 + c16 * 16;
                *(uint4*)(smem + OFF_AH + SWZ(ao)) = vh;
                *(uint4*)(smem + OFF_AL + SWZ(ao)) = vl;
            }
            __syncthreads();

            // ---- per-warp HMMA over 4 c16 steps ----
            #pragma unroll
            for (int q = 0; q < 4; ++q) {
                uint32_t ah[2][4], al[2][4];
                #pragma unroll
                for (int mt = 0; mt < 2; ++mt) {
                    int t   = lane >> 3;
                    int row = k_w + mt * 16 + (lane & 7) + ((t & 1) * 8);
                    int off = row * 128 + q * 32 + ((t >> 1) * 16);
                    ldsm_x4(ah[mt], sb + OFF_AH + SWZ(off));
                    ldsm_x4(al[mt], sb + OFF_AL + SWZ(off));
                }
                uint32_t bh[2][4], bl[2][4];
                #pragma unroll
                for (int nt2 = 0; nt2 < 2; ++nt2) {
                    int nrow = px_w + nt2 * 16 + ((lane >> 4) * 8) + (lane & 7);
                    int off  = nrow * 128 + q * 32 + (((lane >> 3) & 1) * 16);
                    ldsm_x4(bh[nt2], sb + OFF_BH + SWZ(off));
                    ldsm_x4(bl[nt2], sb + OFF_BL + SWZ(off));
                }
                #pragma unroll
                for (int mt = 0; mt < 2; ++mt)
                    #pragma unroll
                    for (int nt = 0; nt < 4; ++nt) {
                        const uint32_t* Bh = &bh[nt >> 1][(nt & 1) * 2];
                        const uint32_t* Bl = &bl[nt >> 1][(nt & 1) * 2];
                        mma_bf16(acc[mt][nt], ah[mt], Bh);   // hi*hi
                        mma_bf16(acc[mt][nt], ah[mt], Bl);   // hi*lo
                        mma_bf16(acc[mt][nt], al[mt], Bh);   // lo*hi
                    }
            }
            __syncthreads();   // protect A/B tiles before next rs overwrites
        }
    }

    // ---- epilogue: bias + direct float2 stores from fragments ----
    const int g = lane >> 2, tig = lane & 3;
    #pragma unroll
    for (int mt = 0; mt < 2; ++mt)
        #pragma unroll
        for (int nt = 0; nt < 4; ++nt)
            #pragma unroll
            for (int half = 0; half < 2; ++half) {
                int krow = k_w + mt * 16 + g + half * 8;
                float b = __ldg(&bias[k0 + krow]);
                int pxl = px_w + nt * 8 + tig * 2;
                int py = pxl >> 3, pxx = pxl & 7;
                float2 v;
                v.x = acc[mt][nt][half * 2 + 0] + b;
                v.y = acc[mt][nt][half * 2 + 1] + b;
                *(float2*)&out[((size_t)(n * 256 + k0 + krow)) * 3136 +
                               (ph + py) * 56 + (pw + pxx)] = v;
            }
}

extern "C" void kernel_launch(void* const* d_in, const int* in_sizes, int n_in,
                              void* d_out, int out_size) {
    const float* x    = (const float*)d_in[0];   // [32,128,56,56]
    const float* wgt  = (const float*)d_in[1];   // [256,128,3,3]
    const float* bias = (const float*)d_in[2];   // [256]
    float* out = (float*)d_out;                  // [32,256,56,56]

    prep_w_kernel<<<1152, 256>>>(wgt);

    cudaFuncSetAttribute(conv_mma_kernel,
                         cudaFuncAttributeMaxDynamicSharedMemorySize, SMEM_TOTAL);
    dim3 grid(2, 49, 32);   // (k-block of 128, pixel tile 8x8, n)
    conv_mma_kernel<<<grid, 256, SMEM_TOTAL>>>(x, bias, out);
}